// round 14
// baseline (speedup 1.0000x reference)
#include <cuda_runtime.h>

#define FH 50
#define FW 50
#define CH 256
#define BATCH 4
#define NROI 1024
#define HOUT 7
#define WOUT 7
#define NBIN (HOUT*WOUT)
#define RATIO (1.0f/32.0f)
#define NGRP 4
#define TPB (128*NGRP)
#define HW (FH*FW)

typedef unsigned long long u64;

// smem: tile[CH*NBIN] f32 + oA int4[NBIN] + wy float4[NBIN] + 2x wx ulonglong2[NBIN]
#define SMEM_BYTES (CH*NBIN*4 + NBIN*16*4)

// Features transposed to BHWC so channel reads are contiguous.
__device__ float g_feats[BATCH * HW * CH];

// ---------------------------------------------------------------------------
// packed f32x2 helpers (FFMA2/FMUL2 — only reachable via PTX)
// ---------------------------------------------------------------------------
__device__ __forceinline__ u64 pkdup(float x) {
    u64 r; asm("mov.b64 %0, {%1,%1};" : "=l"(r) : "f"(x)); return r;
}
__device__ __forceinline__ u64 mul2(u64 a, u64 b) {
    u64 r; asm("mul.rn.f32x2 %0, %1, %2;" : "=l"(r) : "l"(a), "l"(b)); return r;
}
__device__ __forceinline__ u64 fma2(u64 a, u64 b, u64 c) {
    u64 r; asm("fma.rn.f32x2 %0, %1, %2, %3;" : "=l"(r) : "l"(a), "l"(b), "l"(c)); return r;
}
__device__ __forceinline__ float2 asf2(u64 v) {
    union { u64 u; float2 f; } c; c.u = v; return c.f;
}

// ---------------------------------------------------------------------------
// Kernel 1: BCHW -> BHWC, classic 32x32 smem-tiled transpose per batch.
// ---------------------------------------------------------------------------
__global__ void transpose_feats_kernel(const float* __restrict__ in) {
    __shared__ float t[32][33];
    int b  = blockIdx.z;
    int c0 = blockIdx.x * 32;
    int p0 = blockIdx.y * 32;
    const float* src = in + (size_t)b * CH * HW;
    float* dst = g_feats + (size_t)b * HW * CH;

    int p = p0 + threadIdx.x;
#pragma unroll
    for (int i = 0; i < 32; i += 8) {
        int c = c0 + threadIdx.y + i;
        if (p < HW)
            t[threadIdx.y + i][threadIdx.x] = src[(size_t)c * HW + p];
    }
    __syncthreads();
    int c = c0 + threadIdx.x;
#pragma unroll
    for (int i = 0; i < 32; i += 8) {
        int pp = p0 + threadIdx.y + i;
        if (pp < HW)
            dst[(size_t)pp * CH + c] = t[threadIdx.x][threadIdx.y + i];
    }
}

// ---------------------------------------------------------------------------
// Kernel 2: RoIAlign. One block per FULL roi (grid 1024, 512 thr; regs target
// <=42 so 3 CTAs/SM co-reside, occ ~65% — verified R12/R13). Factorized
// bilinear with adjacency reuse; x-interp in packed f32x2 (corners are
// already 64-bit pairs). dcol/drow are single bits {0,128}/{0,6400} packed
// with the flags into oA.w bits 24..27 (offset needs only 19 bits).
// ---------------------------------------------------------------------------
__global__ __launch_bounds__(TPB, 2)
void roialign_kernel(const float* __restrict__ rois,
                     float* __restrict__ out) {
    extern __shared__ float smem[];
    float*      tile  = smem;                           // [CH][NBIN]
    int4*       g_oA  = (int4*)(smem + CH * NBIN);      // [NBIN] r0c0,r0c1,r1c0,r1c1|flags<<24
    float4*     g_wy  = (float4*)(g_oA + NBIN);         // [NBIN] wyb0,wyt0,wyb1,wyt1 (0 if invalid)
    ulonglong2* g_wx0 = (ulonglong2*)(g_wy + NBIN);     // [NBIN] {wxh0 dup, wxl0 dup}
    ulonglong2* g_wx1 = g_wx0 + NBIN;                   // [NBIN] {wxh1 dup, wxl1 dup}

    int r   = blockIdx.x;
    int tid = threadIdx.x;

    int b = (int)__ldg(&rois[r * 5 + 0]);
    const u64* fbu = (const u64*)g_feats + (size_t)b * HW * (CH / 2);

    // ---- Phase A ----
    if (tid < NBIN) {
        float bx1 = fminf(fmaxf(__ldg(&rois[r * 5 + 1]) * RATIO, 0.f), (float)FW);
        float by1 = fminf(fmaxf(__ldg(&rois[r * 5 + 2]) * RATIO, 0.f), (float)FH);
        float bx2 = fminf(fmaxf(__ldg(&rois[r * 5 + 3]) * RATIO, 0.f), (float)FW);
        float by2 = fminf(fmaxf(__ldg(&rois[r * 5 + 4]) * RATIO, 0.f), (float)FH);
        bool roi_valid = (bx2 - bx1 > 0.f) && (by2 - by1 > 0.f);
        float bin_w = (bx2 - bx1) * (1.0f / WOUT);
        float bin_h = (by2 - by1) * (1.0f / HOUT);

        int i = tid / WOUT;
        int j = tid - i * WOUT;

        float y1u = by1 + (float)i * bin_h;
        float y1b = fminf(fmaxf(y1u, 0.f), (float)FH);
        float y2b = fminf(fmaxf(y1u + bin_h, 0.f), (float)FH);
        float x1u = bx1 + (float)j * bin_w;
        float x1b = fminf(fmaxf(x1u, 0.f), (float)FW);
        float x2b = fminf(fmaxf(x1u + bin_w, 0.f), (float)FW);
        bool valid = roi_valid && (x2b > x1b) && (y2b > y1b);
        float vscale = valid ? 1.f : 0.f;

        int   rowi[4], coli[4];
        float wyv[4], wxv[4];
#pragma unroll
        for (int t = 0; t < 2; t++) {
            float py = y1b + ((float)t + 0.5f) * (bin_h * 0.5f);
            float yl = fminf(fmaxf(floorf(py), 0.f), (float)(FH - 1));
            int ylI = (int)yl;
            int yhI = min(ylI + 1, FH - 1);
            rowi[2 * t + 0] = ylI * FW * (CH / 2);
            rowi[2 * t + 1] = yhI * FW * (CH / 2);
            wyv[2 * t + 0] = (py - yl) * vscale;          // wyb (zeroed if invalid)
            wyv[2 * t + 1] = ((float)yhI - py) * vscale;  // wyt (NOT 1-wyb)

            float px = x1b + ((float)t + 0.5f) * (bin_w * 0.5f);
            float xl = fminf(fmaxf(floorf(px), 0.f), (float)(FW - 1));
            int xlI = (int)xl;
            int xhI = min(xlI + 1, FW - 1);
            coli[2 * t + 0] = xlI * (CH / 2);
            coli[2 * t + 1] = xhI * (CH / 2);
            wxv[2 * t + 0] = px - xl;          // wxh
            wxv[2 * t + 1] = (float)xhI - px;  // wxl
        }
        int sameX  = (coli[2] == coli[0]);    // xl1==xl0 (else xl1==xh0)
        int sameY  = (rowi[2] == rowi[0]);
        int dcolNZ = (coli[3] != coli[1]);    // dcol == CH/2 when set, else 0
        int drowNZ = (rowi[3] != rowi[1]);    // drow == FW*CH/2 when set, else 0
        int flags  = sameX | (sameY << 1) | (dcolNZ << 2) | (drowNZ << 3);
        // base 2x2 corners pre-summed; flags ride in oA.w bits 24+ (offset < 2^19)
        g_oA[tid] = make_int4(rowi[0] + coli[0], rowi[0] + coli[1],
                              rowi[1] + coli[0],
                              (rowi[1] + coli[1]) | (flags << 24));
        g_wy[tid] = make_float4(wyv[0], wyv[1], wyv[2], wyv[3]);
        ulonglong2 w;
        w.x = pkdup(wxv[0]); w.y = pkdup(wxv[1]); g_wx0[tid] = w;
        w.x = pkdup(wxv[2]); w.y = pkdup(wxv[3]); g_wx1[tid] = w;
    }
    __syncthreads();

    // ---- Phase B ----
    int c2  = tid & 127;       // channel pair 0..127
    int grp = tid >> 7;        // bin group 0..3
    const u64* fb2 = fbu + c2;

    for (int k = grp; k < NBIN; k += NGRP) {
        int4       oA  = g_oA[k];
        float4     wy  = g_wy[k];
        ulonglong2 wxa = g_wx0[k];    // {xh0, xl0} duplicated
        ulonglong2 wxb = g_wx1[k];    // {xh1, xl1} duplicated
        int fl  = ((unsigned)oA.w) >> 24;
        int o11 = oA.w & 0x00FFFFFF;
        bool sameX = fl & 1;
        bool sameY = fl & 2;

        // Base 2x2 corners — always needed.
        u64 f00 = fb2[oA.x];
        u64 f01 = fb2[oA.y];
        u64 f10 = fb2[oA.z];
        u64 f11 = fb2[o11];

        // Packed x-interp for rows r0 (A) and r1 (B).
        u64 hA0 = fma2(wxa.x, f01, mul2(wxa.y, f00));
        u64 hB0 = fma2(wxa.x, f11, mul2(wxa.y, f10));
        u64 hA1, hB1;
        if (sameX) {
            hA1 = fma2(wxb.x, f01, mul2(wxb.y, f00));
            hB1 = fma2(wxb.x, f11, mul2(wxb.y, f10));
        } else {              // xl1 == xh0: only column xh1 is new
            int dcol = (fl & 4) ? (CH / 2) : 0;
            u64 f02 = fb2[oA.y + dcol];
            u64 f12 = fb2[o11 + dcol];
            hA1 = fma2(wxb.x, f02, mul2(wxb.y, f01));
            hB1 = fma2(wxb.x, f12, mul2(wxb.y, f11));
        }

        float2 a0 = asf2(hA0), b0 = asf2(hB0);
        float2 a1 = asf2(hA1), b1 = asf2(hB1);

        // ty=0 samples (first one initializes the max directly).
        float m0 = wy.x * b0.x + wy.y * a0.x;
        float m1 = wy.x * b0.y + wy.y * a0.y;
        m0 = fmaxf(m0, wy.x * b1.x + wy.y * a1.x);
        m1 = fmaxf(m1, wy.x * b1.y + wy.y * a1.y);

        // ty=1 samples
        if (sameY) {          // rows identical: reuse hA/hB with wy1 weights
            m0 = fmaxf(m0, wy.z * b0.x + wy.w * a0.x);
            m1 = fmaxf(m1, wy.z * b0.y + wy.w * a0.y);
            m0 = fmaxf(m0, wy.z * b1.x + wy.w * a1.x);
            m1 = fmaxf(m1, wy.z * b1.y + wy.w * a1.y);
        } else {              // yl1 == yh0: top row r1 (B), bottom row r2 (C)
            int drow = (fl & 8) ? (FW * (CH / 2)) : 0;
            u64 f20 = fb2[oA.z + drow];
            u64 f21 = fb2[o11 + drow];
            u64 hC0 = fma2(wxa.x, f21, mul2(wxa.y, f20));
            u64 hC1;
            if (sameX) {
                hC1 = fma2(wxb.x, f21, mul2(wxb.y, f20));
            } else {
                int dcol = (fl & 4) ? (CH / 2) : 0;
                u64 f22 = fb2[o11 + drow + dcol];
                hC1 = fma2(wxb.x, f22, mul2(wxb.y, f21));
            }
            float2 c0 = asf2(hC0), c1 = asf2(hC1);
            m0 = fmaxf(m0, wy.z * c0.x + wy.w * b0.x);
            m1 = fmaxf(m1, wy.z * c0.y + wy.w * b0.y);
            m0 = fmaxf(m0, wy.z * c1.x + wy.w * b1.x);
            m1 = fmaxf(m1, wy.z * c1.y + wy.w * b1.y);
        }

        tile[(2 * c2 + 0) * NBIN + k] = m0;
        tile[(2 * c2 + 1) * NBIN + k] = m1;
    }
    __syncthreads();

    // ---- Phase C: tile[c*49 + k] is exactly (N,C,7,7) order for this roi ----
    float4* dst4       = (float4*)(out + (size_t)r * CH * NBIN);
    const float4* src4 = (const float4*)tile;
    for (int idx = tid; idx < CH * NBIN / 4; idx += blockDim.x)
        dst4[idx] = src4[idx];
}

extern "C" void kernel_launch(void* const* d_in, const int* in_sizes, int n_in,
                              void* d_out, int out_size) {
    const float* feats = (const float*)d_in[0];   // (4,256,50,50) f32
    const float* rois  = (const float*)d_in[1];   // (1024,5) f32
    float* out = (float*)d_out;                   // (1024,256,7,7) f32

    cudaFuncSetAttribute(roialign_kernel,
                         cudaFuncAttributeMaxDynamicSharedMemorySize, SMEM_BYTES);

    dim3 tgrid(CH / 32, (HW + 31) / 32, BATCH);
    dim3 tblk(32, 8);
    transpose_feats_kernel<<<tgrid, tblk>>>(feats);
    roialign_kernel<<<NROI, TPB, SMEM_BYTES>>>(rois, out);
}

// round 15
// speedup vs baseline: 1.0091x; 1.0091x over previous
#include <cuda_runtime.h>

#define FH 50
#define FW 50
#define CH 256
#define BATCH 4
#define NROI 1024
#define HOUT 7
#define WOUT 7
#define NBIN (HOUT*WOUT)
#define RATIO (1.0f/32.0f)
#define NGRP 4
#define TPB (128*NGRP)
#define HW (FH*FW)

// smem: tile[CH*NBIN] f32 + oA int4[NBIN] + wy float4[NBIN] + wx float4[NBIN]
#define SMEM_BYTES (CH*NBIN*4 + NBIN*16*3)

// Features transposed to BHWC so channel reads are contiguous.
__device__ float g_feats[BATCH * HW * CH];

// ---------------------------------------------------------------------------
// Kernel 1: BCHW -> BHWC, classic 32x32 smem-tiled transpose per batch.
// ---------------------------------------------------------------------------
__global__ void transpose_feats_kernel(const float* __restrict__ in) {
    __shared__ float t[32][33];
    int b  = blockIdx.z;
    int c0 = blockIdx.x * 32;
    int p0 = blockIdx.y * 32;
    const float* src = in + (size_t)b * CH * HW;
    float* dst = g_feats + (size_t)b * HW * CH;

    int p = p0 + threadIdx.x;
#pragma unroll
    for (int i = 0; i < 32; i += 8) {
        int c = c0 + threadIdx.y + i;
        if (p < HW)
            t[threadIdx.y + i][threadIdx.x] = src[(size_t)c * HW + p];
    }
    __syncthreads();
    int c = c0 + threadIdx.x;
#pragma unroll
    for (int i = 0; i < 32; i += 8) {
        int pp = p0 + threadIdx.y + i;
        if (pp < HW)
            dst[(size_t)pp * CH + c] = t[threadIdx.x][threadIdx.y + i];
    }
}

// x-interp on a channel pair: xh*fh + xl*fl (reference expression form)
__device__ __forceinline__ float2 xin(float xh, float xl, float2 fh, float2 fl) {
    float2 r;
    r.x = xh * fh.x + xl * fl.x;
    r.y = xh * fh.y + xl * fl.y;
    return r;
}
// y-combine + max accumulate
#define YMAX(m0, m1, yb, yt, hb, ht)                   \
    do {                                               \
        m0 = fmaxf(m0, (yb) * (hb).x + (yt) * (ht).x); \
        m1 = fmaxf(m1, (yb) * (hb).y + (yt) * (ht).y); \
    } while (0)

// ---------------------------------------------------------------------------
// Kernel 2: RoIAlign. One block per FULL roi (grid 1024, 512 thr; regs <=42
// => 3 CTAs/SM co-reside, occ ~65% — verified R12/R13; f32x2 math is
// blacklisted: it costs ~6 regs and drops the 3rd CTA, R5/R14). R13 scalar
// structure with the fd vector folded into oA.w bits 24..27 (offset < 2^19;
// dcol/drow are single bits since cells are adjacent or clamp-equal):
// Phase B does 3 LDS.128 per bin instead of 4.
// ---------------------------------------------------------------------------
__global__ __launch_bounds__(TPB, 2)
void roialign_kernel(const float* __restrict__ rois,
                     float* __restrict__ out) {
    extern __shared__ float smem[];
    float*  tile  = smem;                               // [CH][NBIN]
    int4*   g_oA  = (int4*)(smem + CH * NBIN);          // [NBIN] r0c0,r0c1,r1c0,r1c1|flags<<24
    float4* g_wy  = (float4*)(g_oA + NBIN);             // [NBIN] wyb0,wyt0,wyb1,wyt1 (0 if invalid)
    float4* g_wx  = g_wy + NBIN;                        // [NBIN] wxh0,wxl0,wxh1,wxl1

    int r   = blockIdx.x;
    int tid = threadIdx.x;

    int b = (int)__ldg(&rois[r * 5 + 0]);
    const float2* fbase = (const float2*)g_feats + (size_t)b * HW * (CH / 2);

    // ---- Phase A ----
    if (tid < NBIN) {
        float bx1 = fminf(fmaxf(__ldg(&rois[r * 5 + 1]) * RATIO, 0.f), (float)FW);
        float by1 = fminf(fmaxf(__ldg(&rois[r * 5 + 2]) * RATIO, 0.f), (float)FH);
        float bx2 = fminf(fmaxf(__ldg(&rois[r * 5 + 3]) * RATIO, 0.f), (float)FW);
        float by2 = fminf(fmaxf(__ldg(&rois[r * 5 + 4]) * RATIO, 0.f), (float)FH);
        bool roi_valid = (bx2 - bx1 > 0.f) && (by2 - by1 > 0.f);
        float bin_w = (bx2 - bx1) * (1.0f / WOUT);
        float bin_h = (by2 - by1) * (1.0f / HOUT);

        int i = tid / WOUT;
        int j = tid - i * WOUT;

        float y1u = by1 + (float)i * bin_h;
        float y1b = fminf(fmaxf(y1u, 0.f), (float)FH);
        float y2b = fminf(fmaxf(y1u + bin_h, 0.f), (float)FH);
        float x1u = bx1 + (float)j * bin_w;
        float x1b = fminf(fmaxf(x1u, 0.f), (float)FW);
        float x2b = fminf(fmaxf(x1u + bin_w, 0.f), (float)FW);
        bool valid = roi_valid && (x2b > x1b) && (y2b > y1b);
        float vscale = valid ? 1.f : 0.f;

        int   rowi[4], coli[4];
        float wyv[4], wxv[4];
#pragma unroll
        for (int t = 0; t < 2; t++) {
            float py = y1b + ((float)t + 0.5f) * (bin_h * 0.5f);
            float yl = fminf(fmaxf(floorf(py), 0.f), (float)(FH - 1));
            int ylI = (int)yl;
            int yhI = min(ylI + 1, FH - 1);
            rowi[2 * t + 0] = ylI * FW * (CH / 2);
            rowi[2 * t + 1] = yhI * FW * (CH / 2);
            wyv[2 * t + 0] = (py - yl) * vscale;          // wyb (zeroed if invalid)
            wyv[2 * t + 1] = ((float)yhI - py) * vscale;  // wyt (NOT 1-wyb)

            float px = x1b + ((float)t + 0.5f) * (bin_w * 0.5f);
            float xl = fminf(fmaxf(floorf(px), 0.f), (float)(FW - 1));
            int xlI = (int)xl;
            int xhI = min(xlI + 1, FW - 1);
            coli[2 * t + 0] = xlI * (CH / 2);
            coli[2 * t + 1] = xhI * (CH / 2);
            wxv[2 * t + 0] = px - xl;          // wxh
            wxv[2 * t + 1] = (float)xhI - px;  // wxl
        }
        int sameX  = (coli[2] == coli[0]);    // xl1==xl0 (else xl1==xh0)
        int sameY  = (rowi[2] == rowi[0]);
        int dcolNZ = (coli[3] != coli[1]);    // dcol == CH/2 when set, else 0
        int drowNZ = (rowi[3] != rowi[1]);    // drow == FW*CH/2 when set, else 0
        int flags  = sameX | (sameY << 1) | (dcolNZ << 2) | (drowNZ << 3);
        // base 2x2 corners pre-summed; flags in oA.w bits 24+ (offset < 2^19)
        g_oA[tid] = make_int4(rowi[0] + coli[0], rowi[0] + coli[1],
                              rowi[1] + coli[0],
                              (rowi[1] + coli[1]) | (flags << 24));
        g_wy[tid] = make_float4(wyv[0], wyv[1], wyv[2], wyv[3]);
        g_wx[tid] = make_float4(wxv[0], wxv[1], wxv[2], wxv[3]);
    }
    __syncthreads();

    // ---- Phase B ----
    int c2  = tid & 127;       // channel pair 0..127
    int grp = tid >> 7;        // bin group 0..3
    const float2* fb2 = fbase + c2;
    float* trow0 = tile + (2 * c2 + 0) * NBIN;
    float* trow1 = tile + (2 * c2 + 1) * NBIN;

    for (int k = grp; k < NBIN; k += NGRP) {
        int4   oA = g_oA[k];
        float4 wy = g_wy[k];
        float4 wx = g_wx[k];
        int fl  = ((unsigned)oA.w) >> 24;
        int o11 = oA.w & 0x00FFFFFF;
        bool sameX = fl & 1;
        bool sameY = fl & 2;

        // Base 2x2 corners — always needed.
        float2 f00 = fb2[oA.x];
        float2 f01 = fb2[oA.y];
        float2 f10 = fb2[oA.z];
        float2 f11 = fb2[o11];

        // x-interp for rows r0 (A) and r1 (B), both x-samples.
        float2 hA0 = xin(wx.x, wx.y, f01, f00);
        float2 hB0 = xin(wx.x, wx.y, f11, f10);
        float2 hA1, hB1;
        if (sameX) {
            hA1 = xin(wx.z, wx.w, f01, f00);
            hB1 = xin(wx.z, wx.w, f11, f10);
        } else {              // xl1 == xh0: only column xh1 is new
            int dcol = (fl & 4) ? (CH / 2) : 0;
            float2 f02 = fb2[oA.y + dcol];
            float2 f12 = fb2[o11 + dcol];
            hA1 = xin(wx.z, wx.w, f02, f01);
            hB1 = xin(wx.z, wx.w, f12, f11);
        }

        // ty=0 samples: first one initializes the max directly.
        float m0 = wy.x * hB0.x + wy.y * hA0.x;
        float m1 = wy.x * hB0.y + wy.y * hA0.y;
        YMAX(m0, m1, wy.x, wy.y, hB1, hA1);

        // ty=1 samples
        if (sameY) {          // rows identical: reuse hA/hB with wy1 weights
            YMAX(m0, m1, wy.z, wy.w, hB0, hA0);
            YMAX(m0, m1, wy.z, wy.w, hB1, hA1);
        } else {              // yl1 == yh0: top row r1 (B), bottom row r2 (C)
            int drow = (fl & 8) ? (FW * (CH / 2)) : 0;
            float2 f20 = fb2[oA.z + drow];
            float2 f21 = fb2[o11 + drow];
            float2 hC0 = xin(wx.x, wx.y, f21, f20);
            float2 hC1;
            if (sameX) {
                hC1 = xin(wx.z, wx.w, f21, f20);
            } else {
                int dcol = (fl & 4) ? (CH / 2) : 0;
                float2 f22 = fb2[o11 + drow + dcol];
                hC1 = xin(wx.z, wx.w, f22, f21);
            }
            YMAX(m0, m1, wy.z, wy.w, hC0, hB0);
            YMAX(m0, m1, wy.z, wy.w, hC1, hB1);
        }

        trow0[k] = m0;
        trow1[k] = m1;
    }
    __syncthreads();

    // ---- Phase C: tile[c*49 + k] is exactly (N,C,7,7) order for this roi ----
    float4* dst4       = (float4*)(out + (size_t)r * CH * NBIN);
    const float4* src4 = (const float4*)tile;
    for (int idx = tid; idx < CH * NBIN / 4; idx += blockDim.x)
        dst4[idx] = src4[idx];
}

extern "C" void kernel_launch(void* const* d_in, const int* in_sizes, int n_in,
                              void* d_out, int out_size) {
    const float* feats = (const float*)d_in[0];   // (4,256,50,50) f32
    const float* rois  = (const float*)d_in[1];   // (1024,5) f32
    float* out = (float*)d_out;                   // (1024,256,7,7) f32

    cudaFuncSetAttribute(roialign_kernel,
                         cudaFuncAttributeMaxDynamicSharedMemorySize, SMEM_BYTES);

    dim3 tgrid(CH / 32, (HW + 31) / 32, BATCH);
    dim3 tblk(32, 8);
    transpose_feats_kernel<<<tgrid, tblk>>>(feats);
    roialign_kernel<<<NROI, TPB, SMEM_BYTES>>>(rois, out);
}